// round 1
// baseline (speedup 1.0000x reference)
#include <cuda_runtime.h>

#define L   30
#define CHN 128
#define RS  132   // padded row stride (floats) for [30][128] tiles
#define DBS 44    // padded row stride for dt/B/C [30][40] tile
#define NSEQ 4000 // BSZ*TT = 8*500

typedef unsigned long long ull;

__device__ __forceinline__ ull fma2(ull a, ull b, ull c) {
    ull d;
    asm("fma.rn.f32x2 %0, %1, %2, %3;" : "=l"(d) : "l"(a), "l"(b), "l"(c));
    return d;
}
__device__ __forceinline__ float sum2(ull v) {
    float lo = __uint_as_float((unsigned)(v & 0xffffffffull));
    float hi = __uint_as_float((unsigned)(v >> 32));
    return lo + hi;
}

struct DirW {
    const float *in_w, *conv_w, *conv_b, *x_w, *dt_w, *dt_b, *A_log, *D, *out_w;
};

__global__ __launch_bounds__(128, 2)
void bimamba_kernel(const float* __restrict__ x,
                    const float* __restrict__ norm_w, const float* __restrict__ norm_b,
                    DirW F, DirW Bw,
                    const float* __restrict__ comb_w, const float* __restrict__ comb_b,
                    float* __restrict__ out)
{
    extern __shared__ float sm[];
    float* s_xt  = sm;                 // [30][RS] residual input
    float* s_xn  = s_xt + L*RS;        // [30][RS] layernormed
    float* s_u   = s_xn + L*RS;        // [30][RS] u -> silu(conv(u))
    float* s_z   = s_u  + L*RS;        // [30][RS] z -> y (scan output)
    float* s_of  = s_z  + L*RS;        // [30][RS] fwd out_proj (global order)
    float* s_ob  = s_of + L*RS;        // [30][RS] bwd out_proj (global order)
    float* s_dbc = s_ob + L*RS;        // [30][DBS] dt(8) | B(16) | C(16)
    float* s_stat= s_dbc + L*DBS;      // [30][2] mean, rstd

    const int n    = threadIdx.x;
    const int wid  = n >> 5;
    const int lane = n & 31;
    const int b    = blockIdx.x / 500;
    const int t    = blockIdx.x % 500;

    // ---- load x tile: xt[k][n] = x[b][n][t][k] (30 contiguous floats/thread) ----
    {
        const float* src = x + (((size_t)(b * CHN + n)) * 500 + t) * L;
        #pragma unroll
        for (int k = 0; k < L; k++) s_xt[k*RS + n] = src[k];
    }
    __syncthreads();

    // ---- layernorm over channels, per band k ----
    for (int k = wid; k < L; k += 4) {
        float v0 = s_xt[k*RS + lane];
        float v1 = s_xt[k*RS + lane + 32];
        float v2 = s_xt[k*RS + lane + 64];
        float v3 = s_xt[k*RS + lane + 96];
        float s  = v0 + v1 + v2 + v3;
        float ss = v0*v0 + v1*v1 + v2*v2 + v3*v3;
        #pragma unroll
        for (int o = 16; o; o >>= 1) {
            s  += __shfl_xor_sync(0xffffffffu, s,  o);
            ss += __shfl_xor_sync(0xffffffffu, ss, o);
        }
        if (lane == 0) {
            float mean = s * (1.f / CHN);
            float var  = ss * (1.f / CHN) - mean * mean;
            s_stat[2*k]     = mean;
            s_stat[2*k + 1] = rsqrtf(var + 1e-5f);
        }
    }
    __syncthreads();
    {
        float nw = norm_w[n], nb = norm_b[n];
        #pragma unroll
        for (int k = 0; k < L; k++) {
            float m = s_stat[2*k], r = s_stat[2*k + 1];
            s_xn[k*RS + n] = (s_xt[k*RS + n] - m) * r * nw + nb;
        }
    }
    __syncthreads();

    // ================= two directions =================
    #pragma unroll 1
    for (int dir = 0; dir < 2; dir++) {
        const DirW W = dir ? Bw : F;

        // ---- in_proj: u (half 0) and z (half 1); bwd reads xn reversed ----
        #pragma unroll 1
        for (int half = 0; half < 2; half++) {
            const float* wrow = W.in_w + (half * CHN + n) * CHN;
            ull acc[L];
            #pragma unroll
            for (int k = 0; k < L; k++) acc[k] = 0ull;
            #pragma unroll 4
            for (int m = 0; m < CHN; m += 4) {
                ulonglong2 w2 = *(const ulonglong2*)(wrow + m);
                #pragma unroll
                for (int k = 0; k < L; k++) {
                    int rk = dir ? (L - 1 - k) : k;
                    ulonglong2 x2 = *(const ulonglong2*)&s_xn[rk*RS + m];
                    acc[k] = fma2(x2.x, w2.x, acc[k]);
                    acc[k] = fma2(x2.y, w2.y, acc[k]);
                }
            }
            float* dst = half ? s_z : s_u;
            #pragma unroll
            for (int k = 0; k < L; k++) dst[k*RS + n] = sum2(acc[k]);
        }
        // own-column dependency only: no sync needed before conv

        // ---- causal depthwise conv (len 4) + bias + silu, in place ----
        {
            float c0 = W.conv_w[n*4 + 0], c1 = W.conv_w[n*4 + 1];
            float c2 = W.conv_w[n*4 + 2], c3 = W.conv_w[n*4 + 3];
            float cb = W.conv_b[n];
            float um1 = 0.f, um2 = 0.f, um3 = 0.f;
            #pragma unroll
            for (int k = 0; k < L; k++) {
                float uk = s_u[k*RS + n];
                float v  = cb + c3*uk + c2*um1 + c1*um2 + c0*um3;
                um3 = um2; um2 = um1; um1 = uk;
                float sg = 1.f / (1.f + __expf(-v));
                s_u[k*RS + n] = v * sg;   // u2
            }
        }
        __syncthreads();  // x_proj reads all columns of u2

        // ---- x_proj: x_dbl[k][r] = sum_n u2[k][n] * x_w[r][n]; warp w owns r in [10w,10w+10) ----
        if (lane < L) {
            float acc[10];
            #pragma unroll
            for (int q = 0; q < 10; q++) acc[q] = 0.f;
            const float* urow = s_u + lane * RS;
            #pragma unroll 4
            for (int m = 0; m < CHN; m += 4) {
                float4 uv = *(const float4*)(urow + m);
                #pragma unroll
                for (int q = 0; q < 10; q++) {
                    float4 wv = *(const float4*)(W.x_w + (wid*10 + q) * CHN + m);
                    acc[q] += uv.x*wv.x + uv.y*wv.y + uv.z*wv.z + uv.w*wv.w;
                }
            }
            #pragma unroll
            for (int q = 0; q < 10; q++) s_dbc[lane*DBS + wid*10 + q] = acc[q];
        }
        __syncthreads();

        // ---- selective scan: thread n owns channel n, 16-state recurrence ----
        {
            float A[16], dw[8];
            #pragma unroll
            for (int s = 0; s < 16; s++) A[s] = -__expf(W.A_log[n*16 + s]);
            #pragma unroll
            for (int r = 0; r < 8; r++) dw[r] = W.dt_w[n*8 + r];
            float dtb = W.dt_b[n], Dn = W.D[n];
            float h[16];
            #pragma unroll
            for (int s = 0; s < 16; s++) h[s] = 0.f;
            #pragma unroll 2
            for (int k = 0; k < L; k++) {
                float dta = dtb;
                #pragma unroll
                for (int r = 0; r < 8; r++) dta += s_dbc[k*DBS + r] * dw[r];
                float dt = (dta > 20.f) ? dta : log1pf(__expf(dta));
                float u2 = s_u[k*RS + n];
                float du = dt * u2;
                float y  = 0.f;
                #pragma unroll
                for (int s = 0; s < 16; s++) {
                    float dA = __expf(dt * A[s]);
                    h[s] = fmaf(dA, h[s], du * s_dbc[k*DBS + 8 + s]);
                    y    = fmaf(h[s], s_dbc[k*DBS + 24 + s], y);
                }
                y = fmaf(u2, Dn, y);
                float zv = s_z[k*RS + n];
                float sg = 1.f / (1.f + __expf(-zv));
                s_z[k*RS + n] = y * (zv * sg);   // y stored over z
            }
        }
        __syncthreads();  // out_proj reads all columns of y

        // ---- out_proj; write in GLOBAL band order (reverse for bwd) ----
        {
            const float* wrow = W.out_w + n * CHN;
            ull acc[L];
            #pragma unroll
            for (int k = 0; k < L; k++) acc[k] = 0ull;
            #pragma unroll 4
            for (int m = 0; m < CHN; m += 4) {
                ulonglong2 w2 = *(const ulonglong2*)(wrow + m);
                #pragma unroll
                for (int k = 0; k < L; k++) {
                    ulonglong2 y2 = *(const ulonglong2*)&s_z[k*RS + m];
                    acc[k] = fma2(y2.x, w2.x, acc[k]);
                    acc[k] = fma2(y2.y, w2.y, acc[k]);
                }
            }
            float* dst = dir ? s_ob : s_of;
            #pragma unroll
            for (int k = 0; k < L; k++) {
                int rk = dir ? (L - 1 - k) : k;
                dst[rk*RS + n] = sum2(acc[k]);
            }
        }
        __syncthreads();
    }

    // ---- combine: concat(out_f,out_b) @ Wc^T + bias + residual; store transposed back ----
    {
        const float* wrow = comb_w + n * (2 * CHN);
        ull acc[L];
        #pragma unroll
        for (int k = 0; k < L; k++) acc[k] = 0ull;
        #pragma unroll 4
        for (int m = 0; m < CHN; m += 4) {
            ulonglong2 wf = *(const ulonglong2*)(wrow + m);
            ulonglong2 wb = *(const ulonglong2*)(wrow + CHN + m);
            #pragma unroll
            for (int k = 0; k < L; k++) {
                ulonglong2 a  = *(const ulonglong2*)&s_of[k*RS + m];
                ulonglong2 bb = *(const ulonglong2*)&s_ob[k*RS + m];
                acc[k] = fma2(a.x,  wf.x, acc[k]);
                acc[k] = fma2(a.y,  wf.y, acc[k]);
                acc[k] = fma2(bb.x, wb.x, acc[k]);
                acc[k] = fma2(bb.y, wb.y, acc[k]);
            }
        }
        float cb = comb_b[n];
        float* dst = out + (((size_t)(b * CHN + n)) * 500 + t) * L;
        #pragma unroll
        for (int k = 0; k < L; k++) dst[k] = sum2(acc[k]) + cb + s_xt[k*RS + n];
    }
}

static const int SMEM_BYTES = (6 * L * RS + L * DBS + 64) * 4;

extern "C" void kernel_launch(void* const* d_in, const int* in_sizes, int n_in,
                              void* d_out, int out_size)
{
    (void)in_sizes; (void)n_in; (void)out_size;
    const float* x      = (const float*)d_in[0];
    const float* norm_w = (const float*)d_in[1];
    const float* norm_b = (const float*)d_in[2];

    DirW F, Bw;
    F.in_w   = (const float*)d_in[3];
    F.conv_w = (const float*)d_in[4];
    F.conv_b = (const float*)d_in[5];
    F.x_w    = (const float*)d_in[6];
    F.dt_w   = (const float*)d_in[7];
    F.dt_b   = (const float*)d_in[8];
    F.A_log  = (const float*)d_in[9];
    F.D      = (const float*)d_in[10];
    F.out_w  = (const float*)d_in[11];
    Bw.in_w   = (const float*)d_in[12];
    Bw.conv_w = (const float*)d_in[13];
    Bw.conv_b = (const float*)d_in[14];
    Bw.x_w    = (const float*)d_in[15];
    Bw.dt_w   = (const float*)d_in[16];
    Bw.dt_b   = (const float*)d_in[17];
    Bw.A_log  = (const float*)d_in[18];
    Bw.D      = (const float*)d_in[19];
    Bw.out_w  = (const float*)d_in[20];
    const float* comb_w = (const float*)d_in[21];
    const float* comb_b = (const float*)d_in[22];

    cudaFuncSetAttribute(bimamba_kernel,
                         cudaFuncAttributeMaxDynamicSharedMemorySize, SMEM_BYTES);
    bimamba_kernel<<<NSEQ, 128, SMEM_BYTES>>>(x, norm_w, norm_b, F, Bw,
                                              comb_w, comb_b, (float*)d_out);
}